// round 3
// baseline (speedup 1.0000x reference)
#include <cuda_runtime.h>
#include <cuda_bf16.h>

// Problem constants (fixed for this dataset instance)
#define NROWS 8192
#define DIN   1024
#define DOUT  4096
#define KSEL  10
#define TCAND 32
#define NEG_SLOPE_F 0.01f
#define GAMMA_F 0.01618f
#define NEG_INF (__int_as_float(0xff800000))

// ---------------- static device scratch (no runtime allocation) ----------------
__device__ float  g_h[(size_t)NROWS * DOUT];        // 128 MB: leaky_relu(X@W^T + b)
__device__ float2 g_cand[(size_t)NROWS * TCAND];    // per-row top-32 (h, idx-as-float-bits)
__device__ float  g_restmax[NROWS];                 // per-row 33rd-largest h

__device__ __forceinline__ bool better(float av, int ai, float bv, int bi) {
    // ordering: value desc, index asc (matches lax.top_k tie-break)
    return (av > bv) || (av == bv && ai < bi);
}

// =====================================================================
// 1) fp32 SGEMM, 128x128 tile, BK=16, 256 threads, 8x8 per thread,
//    double-buffered smem. K accumulated strictly ascending with FFMA
//    (single accumulator per output). Fused bias + leaky_relu -> g_h.
// =====================================================================
__global__ __launch_bounds__(256, 2) void gemm_kernel(
    const float* __restrict__ A,      // X [NROWS, DIN] row-major
    const float* __restrict__ B,      // W [DOUT, DIN] row-major
    const float* __restrict__ bias)   // b [DOUT]
{
    __shared__ __align__(16) float As[2][16][128];
    __shared__ __align__(16) float Bs[2][16][128];

    const int tid = threadIdx.x;
    const int bx = blockIdx.x;  // over DOUT/128
    const int by = blockIdx.y;  // over NROWS/128
    const int tx = tid & 15, ty = tid >> 4;
    const int tm = ty << 3, tn = tx << 3;
    const int lr = tid >> 2;          // 0..63
    const int lc = (tid & 3) << 2;    // 0,4,8,12

    const float* Ap = A + (size_t)(by * 128 + lr) * DIN + lc;
    const float* Bp = B + (size_t)(bx * 128 + lr) * DIN + lc;

    float acc[8][8];
    #pragma unroll
    for (int i = 0; i < 8; i++)
        #pragma unroll
        for (int j = 0; j < 8; j++) acc[i][j] = 0.f;

    // load k-tile 0
    float4 a0 = *(const float4*)(Ap);
    float4 a1 = *(const float4*)(Ap + (size_t)64 * DIN);
    float4 b0 = *(const float4*)(Bp);
    float4 b1 = *(const float4*)(Bp + (size_t)64 * DIN);

    As[0][lc+0][lr]    = a0.x; As[0][lc+1][lr]    = a0.y; As[0][lc+2][lr]    = a0.z; As[0][lc+3][lr]    = a0.w;
    As[0][lc+0][lr+64] = a1.x; As[0][lc+1][lr+64] = a1.y; As[0][lc+2][lr+64] = a1.z; As[0][lc+3][lr+64] = a1.w;
    Bs[0][lc+0][lr]    = b0.x; Bs[0][lc+1][lr]    = b0.y; Bs[0][lc+2][lr]    = b0.z; Bs[0][lc+3][lr]    = b0.w;
    Bs[0][lc+0][lr+64] = b1.x; Bs[0][lc+1][lr+64] = b1.y; Bs[0][lc+2][lr+64] = b1.z; Bs[0][lc+3][lr+64] = b1.w;
    __syncthreads();

    int p = 0;
    const int NT = DIN / 16;
    for (int tile = 0; tile < NT; tile++) {
        if (tile < NT - 1) {
            const float* An = Ap + (tile + 1) * 16;
            const float* Bn = Bp + (tile + 1) * 16;
            a0 = *(const float4*)(An);
            a1 = *(const float4*)(An + (size_t)64 * DIN);
            b0 = *(const float4*)(Bn);
            b1 = *(const float4*)(Bn + (size_t)64 * DIN);
        }
        #pragma unroll
        for (int kk = 0; kk < 16; kk++) {
            float av[8], bv[8];
            *(float4*)(av)     = *(const float4*)&As[p][kk][tm];
            *(float4*)(av + 4) = *(const float4*)&As[p][kk][tm + 4];
            *(float4*)(bv)     = *(const float4*)&Bs[p][kk][tn];
            *(float4*)(bv + 4) = *(const float4*)&Bs[p][kk][tn + 4];
            #pragma unroll
            for (int i = 0; i < 8; i++)
                #pragma unroll
                for (int j = 0; j < 8; j++)
                    acc[i][j] = fmaf(av[i], bv[j], acc[i][j]);
        }
        if (tile < NT - 1) {
            const int q = p ^ 1;
            As[q][lc+0][lr]    = a0.x; As[q][lc+1][lr]    = a0.y; As[q][lc+2][lr]    = a0.z; As[q][lc+3][lr]    = a0.w;
            As[q][lc+0][lr+64] = a1.x; As[q][lc+1][lr+64] = a1.y; As[q][lc+2][lr+64] = a1.z; As[q][lc+3][lr+64] = a1.w;
            Bs[q][lc+0][lr]    = b0.x; Bs[q][lc+1][lr]    = b0.y; Bs[q][lc+2][lr]    = b0.z; Bs[q][lc+3][lr]    = b0.w;
            Bs[q][lc+0][lr+64] = b1.x; Bs[q][lc+1][lr+64] = b1.y; Bs[q][lc+2][lr+64] = b1.z; Bs[q][lc+3][lr+64] = b1.w;
            __syncthreads();
            p = q;
        }
    }

    // epilogue: + bias, leaky_relu (x>=0 ? x : 0.01*x), store to g_h
    float bl[8];
    const float* bp = bias + bx * 128 + tn;
    *(float4*)(bl)     = *(const float4*)(bp);
    *(float4*)(bl + 4) = *(const float4*)(bp + 4);
    float* hp = g_h + (size_t)(by * 128 + tm) * DOUT + bx * 128 + tn;
    #pragma unroll
    for (int i = 0; i < 8; i++) {
        float o[8];
        #pragma unroll
        for (int j = 0; j < 8; j++) {
            float x = acc[i][j] + bl[j];
            o[j] = (x >= 0.f) ? x : NEG_SLOPE_F * x;
        }
        *(float4*)(hp + (size_t)i * DOUT)     = *(float4*)(o);
        *(float4*)(hp + (size_t)i * DOUT + 4) = *(float4*)(o + 4);
    }
}

// =====================================================================
// 2) Per-row exact top-32 of h (value desc, idx asc) + 33rd max.
//    One CTA (256 threads) per row; cached per-thread local max, only
//    the winning thread rescans each round. 33 rounds of block-argmax.
// =====================================================================
__global__ void top32_kernel() {
    __shared__ float sh[DOUT];
    __shared__ float wv[8];
    __shared__ int   wi[8];
    __shared__ int   wt[8];
    __shared__ float bv_s;
    __shared__ int   bi_s;
    __shared__ int   bt_s;

    const int row = blockIdx.x;
    const int tid = threadIdx.x;
    const int lane = tid & 31, wid = tid >> 5;

    const float* src = g_h + (size_t)row * DOUT;
    for (int i = tid; i < DOUT; i += 256) sh[i] = src[i];
    __syncthreads();

    // local max over columns {tid + 256*i} (conflict-free LDS)
    float lv = NEG_INF; int li = 0x7fffffff;
    #pragma unroll
    for (int i = 0; i < DOUT / 256; i++) {
        int c = tid + (i << 8);
        float x = sh[c];
        if (better(x, c, lv, li)) { lv = x; li = c; }
    }

    for (int r = 0; r <= TCAND; r++) {
        float rv = lv; int ri = li; int rt = tid;
        #pragma unroll
        for (int d = 16; d > 0; d >>= 1) {
            float ov = __shfl_xor_sync(0xffffffffu, rv, d);
            int   oi = __shfl_xor_sync(0xffffffffu, ri, d);
            int   ot = __shfl_xor_sync(0xffffffffu, rt, d);
            if (better(ov, oi, rv, ri)) { rv = ov; ri = oi; rt = ot; }
        }
        if (lane == 0) { wv[wid] = rv; wi[wid] = ri; wt[wid] = rt; }
        __syncthreads();
        if (tid < 8) {
            float rv2 = wv[tid]; int ri2 = wi[tid]; int rt2 = wt[tid];
            #pragma unroll
            for (int d = 4; d > 0; d >>= 1) {
                float ov = __shfl_xor_sync(0xffu, rv2, d);
                int   oi = __shfl_xor_sync(0xffu, ri2, d);
                int   ot = __shfl_xor_sync(0xffu, rt2, d);
                if (better(ov, oi, rv2, ri2)) { rv2 = ov; ri2 = oi; rt2 = ot; }
            }
            if (tid == 0) { bv_s = rv2; bi_s = ri2; bt_s = rt2; }
        }
        __syncthreads();
        const float WV = bv_s; const int WI = bi_s; const int WT = bt_s;
        if (r < TCAND) {
            if (tid == 0)
                g_cand[(size_t)row * TCAND + r] = make_float2(WV, __int_as_float(WI));
            if (tid == WT) {
                sh[WI] = NEG_INF;  // remove winner; rescan own slice
                lv = NEG_INF; li = 0x7fffffff;
                #pragma unroll
                for (int i = 0; i < DOUT / 256; i++) {
                    int c = tid + (i << 8);
                    float x = sh[c];
                    if (better(x, c, lv, li)) { lv = x; li = c; }
                }
            }
        } else {
            if (tid == 0) g_restmax[row] = WV;  // 33rd largest
        }
        __syncthreads();
    }
}

// =====================================================================
// 3) Serial scan: ONE warp, 8192 steps. Fast path ranks 32 candidates
//    via shuffle ring; exact full-row fallback when speculation unsound.
// =====================================================================
__device__ void fallback_row(int t, float* __restrict__ out, int* last_sel,
                             const float* PHI, int lane) {
    // exact top-10 of s over all 4096 columns
    float v[10]; int vi[10];
    #pragma unroll
    for (int j = 0; j < 10; j++) { v[j] = NEG_INF; vi[j] = 0x7fffffff; }
    const float* row = g_h + (size_t)t * DOUT;
    for (int c = lane; c < DOUT; c += 32) {
        float h = __ldg(row + c);
        int m = min(t - last_sel[c] - 1, 63);
        float s = h * PHI[m];
        if (better(s, c, v[9], vi[9])) {
            v[9] = s; vi[9] = c;
            #pragma unroll
            for (int j = 9; j > 0; j--) {
                if (better(v[j], vi[j], v[j - 1], vi[j - 1])) {
                    float tv = v[j]; v[j] = v[j - 1]; v[j - 1] = tv;
                    int   ti = vi[j]; vi[j] = vi[j - 1]; vi[j - 1] = ti;
                }
            }
        }
    }
    #pragma unroll 1
    for (int r = 0; r < KSEL; r++) {
        float rv = v[0]; int ri = vi[0];
        #pragma unroll
        for (int d = 16; d > 0; d >>= 1) {
            float ov = __shfl_xor_sync(0xffffffffu, rv, d);
            int   oi = __shfl_xor_sync(0xffffffffu, ri, d);
            if (better(ov, oi, rv, ri)) { rv = ov; ri = oi; }
        }
        if (lane == 0 && rv > 0.f) {
            last_sel[ri] = t;
            out[(size_t)t * DOUT + ri] = 1.0f;
        }
        if (vi[0] == ri) {  // owner pops head (indices unique -> one owner)
            #pragma unroll
            for (int j = 0; j < 9; j++) { v[j] = v[j + 1]; vi[j] = vi[j + 1]; }
            v[9] = NEG_INF; vi[9] = 0x7fffffff;
        }
    }
    __syncwarp();
}

__global__ void scan_kernel(float* __restrict__ out) {
    __shared__ int   last_sel[DOUT];
    __shared__ float PHI[64];
    const int lane = threadIdx.x;  // blockDim = 32

    for (int i = lane; i < DOUT; i += 32) last_sel[i] = -0x40000000;
    if (lane == 0) {
        // PHI[m] = phi value m steps after a selection (fp32-iterated like jnp)
        float x = 0.f;
        for (int m = 0; m < 64; m++) {
            PHI[m] = x;
            x = (x < 1.f) ? fminf(x + GAMMA_F, 1.f) : x;
        }
    }
    __syncwarp();

    float2 c0 = __ldg(&g_cand[lane]);
    float  r0 = __ldg(&g_restmax[0]);
    float2 c1 = __ldg(&g_cand[TCAND + lane]);
    float  r1 = __ldg(&g_restmax[1]);

    for (int t = 0; t < NROWS; t++) {
        const float h  = c0.x;
        const int   idx = __float_as_int(c0.y);
        const float rmax = r0;
        c0 = c1; r0 = r1;
        if (t + 2 < NROWS) {
            c1 = __ldg(&g_cand[(size_t)(t + 2) * TCAND + lane]);
            r1 = __ldg(&g_restmax[t + 2]);
        }

        int m = t - last_sel[idx] - 1;   // >= 0 always
        m = min(m, 63);
        const float s = h * PHI[m];      // phi==1 -> s==h bitwise

        int rank = 0;
        #pragma unroll
        for (int d = 1; d < 32; d++) {
            float so = __shfl_sync(0xffffffffu, s, (lane + d) & 31);
            int   io = __shfl_sync(0xffffffffu, idx, (lane + d) & 31);
            rank += better(so, io, s, idx) ? 1 : 0;
        }
        // ranks are a permutation of 0..31 (indices unique)
        unsigned bl9 = __ballot_sync(0xffffffffu, rank == 9);
        float s9 = __shfl_sync(0xffffffffu, s, __ffs(bl9) - 1);

        // Sound iff all non-candidates (s <= max(rest_max, 0)) are strictly
        // below the 10th candidate value -> candidate top-10 == global top-10.
        if (s9 > fmaxf(rmax, 0.f)) {
            if (rank < KSEL && s > 0.f) {
                last_sel[idx] = t;
                out[(size_t)t * DOUT + idx] = 1.0f;
            }
        } else {
            fallback_row(t, out, last_sel, PHI, lane);
        }
        __syncwarp();
    }
}

// =====================================================================
// 4) Output zeroing (d_out is poisoned before timing)
// =====================================================================
__global__ void zero_kernel(float4* __restrict__ out4) {
    const size_t base = (size_t)blockIdx.x * 1024 + threadIdx.x;
    const float4 z = make_float4(0.f, 0.f, 0.f, 0.f);
    #pragma unroll
    for (int j = 0; j < 4; j++) out4[base + (size_t)j * 256] = z;
}

// =====================================================================
extern "C" void kernel_launch(void* const* d_in, const int* in_sizes, int n_in,
                              void* d_out, int out_size) {
    const float* X    = (const float*)d_in[0];   // [8192, 1024]
    const float* W    = (const float*)d_in[1];   // [4096, 1024]
    const float* bias = (const float*)d_in[2];   // [4096]
    float* out = (float*)d_out;                  // [8192, 4096]
    (void)in_sizes; (void)n_in; (void)out_size;

    zero_kernel<<<NROWS, 256>>>((float4*)out);
    dim3 g(DOUT / 128, NROWS / 128);
    gemm_kernel<<<g, 256>>>(X, W, bias);
    top32_kernel<<<NROWS, 256>>>();
    scan_kernel<<<1, 32>>>(out);
}

// round 17
// speedup vs baseline: 1.0826x; 1.0826x over previous
#include <cuda_runtime.h>
#include <cuda_bf16.h>
#include <cstdint>

// Problem constants (fixed for this dataset instance)
#define NROWS 8192
#define DIN   1024
#define DOUT  4096
#define KSEL  10
#define TCAND 32
#define NEG_SLOPE_F 0.01f
#define GAMMA_F 0.01618f
#define NEG_INF (__int_as_float(0xff800000))
#define EPS_F 3e-3f      // certified bound on |h_mma - h_exact| (~8 sigma)

// GEMM tiling (single tf32 plane, K = 1024)
#define KT  (DIN / 8)               // 128 k8-tiles
#define GBM 128
#define GBN 256
#define KCH 64
#define NQ  (DIN / KCH)             // 16 chunks
#define A_CH_BYTES (GBM * KCH * 4)  // 32768
#define B_CH_BYTES (GBN * KCH * 4)  // 65536
#define CH_BYTES   (A_CH_BYTES + B_CH_BYTES)
#define SM_BIAS_OFF (2 * CH_BYTES)
#define SM_TOT      (SM_BIAS_OFF + GBN * 4)

// ---------------- static device scratch (no runtime allocation) ----------------
__device__ float  g_h[(size_t)NROWS * DOUT];       // approx h (tf32 MMA)
__device__ float2 g_cand[(size_t)NROWS * TCAND];   // per-row top-32: approx->exact
__device__ float  g_restmax[NROWS];                // approx 33rd-largest h
__device__ float  g_Af[(size_t)(NROWS / 16) * KT * 128];  // 33.5 MB tf32(X) fragmented
__device__ float  g_Bf[(size_t)(DOUT  /  8) * KT *  64];  // 16.8 MB tf32(W) fragmented

__device__ __forceinline__ bool better(float av, int ai, float bv, int bi) {
    return (av > bv) || (av == bv && ai < bi);   // value desc, index asc (lax.top_k)
}

__device__ __forceinline__ float tf32_rna(float x) {
    float y;
    asm("cvt.rna.tf32.f32 %0, %1;" : "=f"(y) : "f"(x));
    return y;
}

#define CP_ASYNC16(dst, src) \
    asm volatile("cp.async.cg.shared.global [%0], [%1], 16;" :: "r"(dst), "l"(src))

__device__ __forceinline__ uint32_t smem_u32(const void* p) {
    uint32_t a;
    asm("{ .reg .u64 t; cvta.to.shared.u64 t, %1; cvt.u32.u64 %0, t; }" : "=r"(a) : "l"(p));
    return a;
}

__device__ __forceinline__ void mma_tf32(float* c, const float* a, const float* b) {
    asm volatile(
        "mma.sync.aligned.m16n8k8.row.col.f32.tf32.tf32.f32 "
        "{%0,%1,%2,%3}, {%4,%5,%6,%7}, {%8,%9}, {%0,%1,%2,%3};"
        : "+f"(c[0]), "+f"(c[1]), "+f"(c[2]), "+f"(c[3])
        : "r"(__float_as_uint(a[0])), "r"(__float_as_uint(a[1])),
          "r"(__float_as_uint(a[2])), "r"(__float_as_uint(a[3])),
          "r"(__float_as_uint(b[0])), "r"(__float_as_uint(b[1])));
}

// fragment-contiguous layouts (validated by R7's 1e-6-accurate h)
__device__ __forceinline__ size_t idxA(int r, int k) {
    int mt = r >> 4, kt = k >> 3, ri = r & 15, ci = k & 7;
    int l = ((ri & 7) << 2) | (ci & 3);
    int v = ((ci >> 2) << 1) | (ri >> 3);
    return (((size_t)mt * KT + kt) << 7) + (l << 2) + v;
}
__device__ __forceinline__ size_t idxB(int n, int k) {
    int nt = n >> 3, kt = k >> 3, ni = n & 7, ci = k & 7;
    int l = (ni << 2) | (ci & 3);
    int v = ci >> 2;
    return (((size_t)nt * KT + kt) << 6) + (l << 1) + v;
}

// ============== 0) tf32 conversion into fragment order ==============
__global__ void splitA_kernel(const float* __restrict__ X) {
    int e = blockIdx.x * 256 + threadIdx.x;
    if (e >= NROWS * DIN) return;
    g_Af[idxA(e >> 10, e & 1023)] = tf32_rna(X[e]);
}
__global__ void splitB_kernel(const float* __restrict__ W) {
    int e = blockIdx.x * 256 + threadIdx.x;
    if (e >= DOUT * DIN) return;
    g_Bf[idxB(e >> 10, e & 1023)] = tf32_rna(W[e]);
}

// ============== 1) tf32 mma.sync GEMM (approx h) ==============
__global__ void __launch_bounds__(256) gemm_mma_kernel(const float* __restrict__ bias) {
    extern __shared__ __align__(1024) char smem[];
    const uint32_t sb = smem_u32(smem);
    const int tid = threadIdx.x;
    const int wid = tid >> 5, lane = tid & 31;
    const int m0t = blockIdx.y * (GBM / 16);
    const int n0t = blockIdx.x * (GBN / 8);
    const int wm = wid & 1, wn = wid >> 1;

    float* sbias = (float*)(smem + SM_BIAS_OFF);
    sbias[tid] = bias[blockIdx.x * GBN + tid];

    auto loadch = [&](int q, int buf) {
        const uint32_t base = sb + buf * CH_BYTES;
        #pragma unroll
        for (int i = 0; i < 8; i++) {
            int u = tid + (i << 8);
            int mi = u >> 8, kt = (u >> 5) & 7, l = u & 31;
            const float* src = g_Af +
                (((size_t)(m0t + mi) * KT + q * 8 + kt) << 7) + (l << 2);
            CP_ASYNC16(base + u * 16, src);
        }
        #pragma unroll
        for (int i = 0; i < 16; i++) {
            int u = tid + (i << 8);
            int ni = u >> 7, kt = (u >> 4) & 7, j = u & 15;
            const float* src = g_Bf +
                (((size_t)(n0t + ni) * KT + q * 8 + kt) << 6) + (j << 2);
            CP_ASYNC16(base + A_CH_BYTES + u * 16, src);
        }
        asm volatile("cp.async.commit_group;" ::: "memory");
    };

    float acc[4][8][4];
    #pragma unroll
    for (int a = 0; a < 4; a++)
        #pragma unroll
        for (int b = 0; b < 8; b++)
            #pragma unroll
            for (int v = 0; v < 4; v++) acc[a][b][v] = 0.f;

    loadch(0, 0);
    loadch(1, 1);

    for (int q = 0; q < NQ; q++) {
        const int buf = q & 1;
        asm volatile("cp.async.wait_group 1;" ::: "memory");
        __syncthreads();
        const char* cb = smem + buf * CH_BYTES;
        #pragma unroll
        for (int kt = 0; kt < 8; kt++) {
            float af[4][4];
            #pragma unroll
            for (int im = 0; im < 4; im++) {
                const float* t = (const float*)(cb + ((((wm * 4 + im) << 3) | kt) << 9)) + (lane << 2);
                float4 v = *(const float4*)t;
                af[im][0] = v.x; af[im][1] = v.y; af[im][2] = v.z; af[im][3] = v.w;
            }
            float bf[8][2];
            #pragma unroll
            for (int in_ = 0; in_ < 8; in_++) {
                const float* t = (const float*)(cb + A_CH_BYTES + ((((wn * 8 + in_) << 3) | kt) << 8)) + (lane << 1);
                float2 v = *(const float2*)t;
                bf[in_][0] = v.x; bf[in_][1] = v.y;
            }
            #pragma unroll
            for (int im = 0; im < 4; im++)
                #pragma unroll
                for (int in_ = 0; in_ < 8; in_++)
                    mma_tf32(acc[im][in_], af[im], bf[in_]);
        }
        __syncthreads();
        if (q + 2 < NQ) loadch(q + 2, buf);
    }

    const int rbase = blockIdx.y * GBM + wm * 64 + (lane >> 2);
    const int cbase = wn * 64 + ((lane & 3) << 1);
    const size_t gc0 = (size_t)blockIdx.x * GBN;
    #pragma unroll
    for (int im = 0; im < 4; im++) {
        #pragma unroll
        for (int in_ = 0; in_ < 8; in_++) {
            const int r = rbase + im * 16;
            const int c = cbase + in_ * 8;
            const float b0 = sbias[c], b1 = sbias[c + 1];
            float x0 = acc[im][in_][0] + b0;
            float x1 = acc[im][in_][1] + b1;
            float x2 = acc[im][in_][2] + b0;
            float x3 = acc[im][in_][3] + b1;
            float2 lo, hi;
            lo.x = (x0 >= 0.f) ? x0 : NEG_SLOPE_F * x0;
            lo.y = (x1 >= 0.f) ? x1 : NEG_SLOPE_F * x1;
            hi.x = (x2 >= 0.f) ? x2 : NEG_SLOPE_F * x2;
            hi.y = (x3 >= 0.f) ? x3 : NEG_SLOPE_F * x3;
            *(float2*)(g_h + (size_t)r * DOUT + gc0 + c)       = lo;
            *(float2*)(g_h + (size_t)(r + 8) * DOUT + gc0 + c) = hi;
        }
    }
}

// ============== 2) per-row top-32 of approx h + approx 33rd ==============
__global__ void top32_kernel() {
    __shared__ float sh[DOUT];
    __shared__ float wv[8];
    __shared__ int   wi[8];
    __shared__ int   wt[8];
    __shared__ float bv_s;
    __shared__ int   bi_s;
    __shared__ int   bt_s;

    const int row = blockIdx.x;
    const int tid = threadIdx.x;
    const int lane = tid & 31, wid = tid >> 5;

    const float* src = g_h + (size_t)row * DOUT;
    for (int i = tid; i < DOUT; i += 256) sh[i] = src[i];
    __syncthreads();

    float lv = NEG_INF; int li = 0x7fffffff;
    #pragma unroll
    for (int i = 0; i < DOUT / 256; i++) {
        int c = tid + (i << 8);
        float x = sh[c];
        if (better(x, c, lv, li)) { lv = x; li = c; }
    }

    for (int r = 0; r <= TCAND; r++) {
        float rv = lv; int ri = li; int rt = tid;
        #pragma unroll
        for (int d = 16; d > 0; d >>= 1) {
            float ov = __shfl_xor_sync(0xffffffffu, rv, d);
            int   oi = __shfl_xor_sync(0xffffffffu, ri, d);
            int   ot = __shfl_xor_sync(0xffffffffu, rt, d);
            if (better(ov, oi, rv, ri)) { rv = ov; ri = oi; rt = ot; }
        }
        if (lane == 0) { wv[wid] = rv; wi[wid] = ri; wt[wid] = rt; }
        __syncthreads();
        if (tid < 8) {
            float rv2 = wv[tid]; int ri2 = wi[tid]; int rt2 = wt[tid];
            #pragma unroll
            for (int d = 4; d > 0; d >>= 1) {
                float ov = __shfl_xor_sync(0xffu, rv2, d);
                int   oi = __shfl_xor_sync(0xffu, ri2, d);
                int   ot = __shfl_xor_sync(0xffu, rt2, d);
                if (better(ov, oi, rv2, ri2)) { rv2 = ov; ri2 = oi; rt2 = ot; }
            }
            if (tid == 0) { bv_s = rv2; bi_s = ri2; bt_s = rt2; }
        }
        __syncthreads();
        const float WV = bv_s; const int WI = bi_s; const int WT = bt_s;
        if (r < TCAND) {
            if (tid == 0)
                g_cand[(size_t)row * TCAND + r] = make_float2(WV, __int_as_float(WI));
            if (tid == WT) {
                sh[WI] = NEG_INF;
                lv = NEG_INF; li = 0x7fffffff;
                #pragma unroll
                for (int i = 0; i < DOUT / 256; i++) {
                    int c = tid + (i << 8);
                    float x = sh[c];
                    if (better(x, c, lv, li)) { lv = x; li = c; }
                }
            }
        } else {
            if (tid == 0) g_restmax[row] = WV;
        }
        __syncthreads();
    }
}

// ============== 2b) exactify candidates: R3-identical ascending-k FFMA ==============
__global__ void __launch_bounds__(128) exact32_kernel(
    const float* __restrict__ X, const float* __restrict__ W,
    const float* __restrict__ bias)
{
    __shared__ float xs[4][DIN];
    const int wid = threadIdx.x >> 5, lane = threadIdx.x & 31;
    const int row = blockIdx.x * 4 + wid;

    for (int k = lane; k < DIN; k += 32) xs[wid][k] = X[(size_t)row * DIN + k];
    __syncwarp();

    float2 cd = g_cand[(size_t)row * TCAND + lane];
    const int idx = __float_as_int(cd.y);
    const float* wr = W + (size_t)idx * DIN;

    float acc = 0.f;
    #pragma unroll 8
    for (int k = 0; k < DIN; k++) acc = fmaf(xs[wid][k], wr[k], acc);
    float x = acc + bias[idx];
    float he = (x >= 0.f) ? x : NEG_SLOPE_F * x;

    // re-sort by (exact h desc, idx asc)
    int rank = 0;
    #pragma unroll
    for (int d = 1; d < 32; d++) {
        float so = __shfl_sync(0xffffffffu, he, (lane + d) & 31);
        int   io = __shfl_sync(0xffffffffu, idx, (lane + d) & 31);
        rank += better(so, io, he, idx) ? 1 : 0;
    }
    __syncwarp();
    g_cand[(size_t)row * TCAND + rank] = make_float2(he, cd.y);
}

// ============== 3) serial scan (exact selections) ==============
__device__ void fallback_row(int t, float* __restrict__ out, int* last_sel,
                             const float* PHI, float* xrow, const float* sbias,
                             const float* __restrict__ X,
                             const float* __restrict__ W,
                             int* scols, int lane)
{
    // load X row for exact chains
    for (int k = lane; k < DIN; k += 32) xrow[k] = X[(size_t)t * DIN + k];
    __syncwarp();

    const float* row = g_h + (size_t)t * DOUT;

    // pass 1: conservative 10th-largest approx s (value only)
    float v[10];
    #pragma unroll
    for (int j = 0; j < 10; j++) v[j] = NEG_INF;
    for (int c = lane; c < DOUT; c += 32) {
        float s = __ldg(row + c) * PHI[min(t - last_sel[c] - 1, 63)];
        if (s > v[9]) {
            v[9] = s;
            #pragma unroll
            for (int j = 9; j > 0; j--)
                if (v[j] > v[j - 1]) { float tv = v[j]; v[j] = v[j - 1]; v[j - 1] = tv; }
        }
    }
    float v10 = NEG_INF;
    #pragma unroll 1
    for (int r = 0; r < KSEL; r++) {
        float rv = v[0];
        #pragma unroll
        for (int d = 16; d > 0; d >>= 1)
            rv = fmaxf(rv, __shfl_xor_sync(0xffffffffu, rv, d));
        if (v[0] == rv) {   // pop (ties over-pop -> conservative threshold)
            #pragma unroll
            for (int j = 0; j < 9; j++) v[j] = v[j + 1];
            v[9] = NEG_INF;
        }
        v10 = rv;
    }
    const float thresh = v10 - 2.0f * EPS_F;

    // pass 2: collect all columns possibly in exact top-10
    int cnt = 0;
    for (int base = 0; base < DOUT; base += 32) {
        int c = base + lane;
        float s = __ldg(row + c) * PHI[min(t - last_sel[c] - 1, 63)];
        bool q = (s >= thresh);
        unsigned bal = __ballot_sync(0xffffffffu, q);
        if (q) {
            int pos = cnt + __popc(bal & ((1u << lane) - 1u));
            if (pos < 32) scols[pos] = c;
        }
        cnt += __popc(bal);
    }
    __syncwarp();

    const int n = min(cnt, 32);
    int c = 0x7fffffff;
    float se = NEG_INF;
    if (lane < n) {
        c = scols[lane];
        const float* wr = W + (size_t)c * DIN;
        float acc = 0.f;
        #pragma unroll 8
        for (int k = 0; k < DIN; k++) acc = fmaf(xrow[k], wr[k], acc);
        float x = acc + sbias[c];
        float he = (x >= 0.f) ? x : NEG_SLOPE_F * x;
        se = he * PHI[min(t - last_sel[c] - 1, 63)];
    }
    int rank = 0;
    #pragma unroll
    for (int d = 1; d < 32; d++) {
        float so = __shfl_sync(0xffffffffu, se, (lane + d) & 31);
        int   io = __shfl_sync(0xffffffffu, c, (lane + d) & 31);
        rank += better(so, io, se, c) ? 1 : 0;
    }
    if (lane < n && rank < KSEL && se > 0.f) {
        last_sel[c] = t;
        out[(size_t)t * DOUT + c] = 1.0f;
    }
    __syncwarp();
}

__global__ void scan_kernel(const float* __restrict__ X,
                            const float* __restrict__ W,
                            const float* __restrict__ bias,
                            float* __restrict__ out)
{
    __shared__ int   last_sel[DOUT];
    __shared__ float sbias[DOUT];
    __shared__ float xrow[DIN];
    __shared__ float PHI[64];
    __shared__ int   scols[32];
    const int lane = threadIdx.x;  // blockDim = 32

    for (int i = lane; i < DOUT; i += 32) { last_sel[i] = -0x40000000; sbias[i] = bias[i]; }
    if (lane == 0) {
        float x = 0.f;
        for (int m = 0; m < 64; m++) {
            PHI[m] = x;
            x = (x < 1.f) ? fminf(x + GAMMA_F, 1.f) : x;
        }
    }
    __syncwarp();

    float2 c0 = __ldg(&g_cand[lane]);
    float  r0 = __ldg(&g_restmax[0]);
    float2 c1 = __ldg(&g_cand[TCAND + lane]);
    float  r1 = __ldg(&g_restmax[1]);

    for (int t = 0; t < NROWS; t++) {
        const float h   = c0.x;
        const int   idx = __float_as_int(c0.y);
        const float rmax = r0;
        c0 = c1; r0 = r1;
        if (t + 2 < NROWS) {
            c1 = __ldg(&g_cand[(size_t)(t + 2) * TCAND + lane]);
            r1 = __ldg(&g_restmax[t + 2]);
        }

        int m = min(t - last_sel[idx] - 1, 63);
        const float phi = PHI[m];
        const float s = h * phi;                 // phi==1 -> s==h bitwise (exact h)

        // all-pairs shuffle-ring rank (field-verified exact in R3, rel_err 0.0)
        int rank = 0;
        #pragma unroll
        for (int d = 1; d < 32; d++) {
            float so = __shfl_sync(0xffffffffu, s, (lane + d) & 31);
            int   io = __shfl_sync(0xffffffffu, idx, (lane + d) & 31);
            rank += better(so, io, s, idx) ? 1 : 0;
        }

        unsigned bl9 = __ballot_sync(0xffffffffu, rank == 9);
        float s9 = __shfl_sync(0xffffffffu, s, __ffs(bl9) - 1);

        // non-candidate exact h <= restmax_approx + EPS; strict separation
        if (s9 > fmaxf(rmax + EPS_F, 0.f)) {
            if (rank < KSEL && s > 0.f) {
                last_sel[idx] = t;
                out[(size_t)t * DOUT + idx] = 1.0f;
            }
        } else {
            fallback_row(t, out, last_sel, PHI, xrow, sbias, X, W, scols, lane);
        }
        __syncwarp();
    }
}

// ============== 4) output zeroing ==============
__global__ void zero_kernel(float4* __restrict__ out4) {
    const size_t base = (size_t)blockIdx.x * 1024 + threadIdx.x;
    const float4 z = make_float4(0.f, 0.f, 0.f, 0.f);
    #pragma unroll
    for (int j = 0; j < 4; j++) out4[base + (size_t)j * 256] = z;
}

// =====================================================================
extern "C" void kernel_launch(void* const* d_in, const int* in_sizes, int n_in,
                              void* d_out, int out_size) {
    const float* X    = (const float*)d_in[0];   // [8192, 1024]
    const float* W    = (const float*)d_in[1];   // [4096, 1024]
    const float* bias = (const float*)d_in[2];   // [4096]
    float* out = (float*)d_out;                  // [8192, 4096]
    (void)in_sizes; (void)n_in; (void)out_size;

    cudaFuncSetAttribute(gemm_mma_kernel,
                         cudaFuncAttributeMaxDynamicSharedMemorySize, SM_TOT);

    zero_kernel<<<NROWS, 256>>>((float4*)out);
    splitA_kernel<<<(NROWS * DIN + 255) / 256, 256>>>(X);
    splitB_kernel<<<(DOUT * DIN + 255) / 256, 256>>>(W);
    dim3 g(DOUT / GBN, NROWS / GBM);
    gemm_mma_kernel<<<g, 256, SM_TOT>>>(bias);
    top32_kernel<<<NROWS, 256>>>();
    exact32_kernel<<<NROWS / 4, 128>>>(X, W, bias);
    scan_kernel<<<1, 32>>>(X, W, bias, out);
}